// round 11
// baseline (speedup 1.0000x reference)
#include <cuda_runtime.h>
#include <math.h>

#define BB   16
#define CC   96
#define C4   384
#define HH   56
#define WW   56
#define HWP  3136          // 56*56
#define CHW  301056        // 96*3136

// natural-major staged tiles (floats), conflict-free pads
#define A_PITCH 36                    // 32 k + pad4  (36 % 32 == 4)
#define B_PITCH 136                   // 128 n + pad8 (136 % 32 == 8)
#define AF_SZ  (96 * A_PITCH)         // 3456
#define BF_SZ  (32 * B_PITCH)         // 4352
#define SMEM_DYN ((2 * (AF_SZ + BF_SZ)) * 4)   // 62464 bytes

// ---------------- scratch (device globals; no allocation) ----------------
__device__ float  g_buf1[BB * CC * HWP];   // dw out
__device__ float  g_buf2[BB * CC * HWP];   // pw out (pre-LN)
__device__ float  g_buf3[BB * C4 * HWP];   // expand+gelu out
__device__ double g_red[BB * 2];           // LN sum / sumsq per batch
__device__ float  g_sv[BB * C4];           // top-singular-value estimates
__device__ float  g_svsum;                 // sum of all sv

// ---------------- helpers ----------------
__device__ __forceinline__ float gelu_tanh_f(float x) {
    const float c = 0.7978845608028654f;
    float x3 = x * x * x;
    return 0.5f * x * (1.0f + tanhf(c * (x + 0.044715f * x3)));
}

__device__ __forceinline__ float tf32r(float x) {
    unsigned u;
    asm("cvt.rna.tf32.f32 %0, %1;" : "=r"(u) : "f"(x));
    return __uint_as_float(u);
}

__device__ __forceinline__ float4 tf32r4(float4 v) {
    return make_float4(tf32r(v.x), tf32r(v.y), tf32r(v.z), tf32r(v.w));
}

__device__ __forceinline__ void mma_tf32(float* c, const unsigned* a, const unsigned* b2) {
    asm volatile("mma.sync.aligned.m16n8k8.row.col.f32.tf32.tf32.f32 "
        "{%0,%1,%2,%3}, {%4,%5,%6,%7}, {%8,%9}, {%0,%1,%2,%3};"
        : "+f"(c[0]), "+f"(c[1]), "+f"(c[2]), "+f"(c[3])
        : "r"(a[0]), "r"(a[1]), "r"(a[2]), "r"(a[3]), "r"(b2[0]), "r"(b2[1]));
}

// ---------------- 1) depthwise 7x7 conv + bias (+ scratch zero-init) ----------------
__global__ void dw_conv_kernel(const float* __restrict__ x,
                               const float* __restrict__ dw_w,
                               const float* __restrict__ dw_b) {
    __shared__ float tile[14][62];
    __shared__ float sw[49];

    const int bc = blockIdx.z;
    const int c  = bc % CC;
    const int y0 = blockIdx.y * 8;
    const int tx = threadIdx.x;
    const int ty = threadIdx.y;
    const int tid = ty * 56 + tx;

    if (bc == 0 && blockIdx.y == 0) {
        if (tid < BB * 2) g_red[tid] = 0.0;
        if (tid == BB * 2) g_svsum = 0.0f;
    }

    const float* src = x + (size_t)bc * HWP;
    if (tid < 49) sw[tid] = dw_w[c * 49 + tid];

    for (int i = tid; i < 14 * 62; i += 448) {
        int r  = i / 62;
        int cx = i - r * 62;
        int gy = y0 - 3 + r;
        int gx = cx - 3;
        float v = 0.0f;
        if (gy >= 0 && gy < HH && gx >= 0 && gx < WW) v = src[gy * WW + gx];
        tile[r][cx] = v;
    }
    __syncthreads();

    float acc = dw_b[c];
    #pragma unroll
    for (int dy = 0; dy < 7; dy++)
        #pragma unroll
        for (int dx = 0; dx < 7; dx++)
            acc = fmaf(sw[dy * 7 + dx], tile[ty + dy][tx + dx], acc);

    g_buf1[(size_t)bc * HWP + (y0 + ty) * WW + tx] = acc;
}

// ---------------- TF32 TC GEMM: natural-major smem, STS.128 staging, LDS.32 gather ----------------
// out[b,m,n] = sum_k W[m,k]*in[b,k,n]
// MODE 0: +bias, fused LN sum/sumsq reduction             (pointwise)
// MODE 1: LN applied to B at staging, +bias, gelu          (expand)
// MODE 2: B scaled by GRN affine, +bias, +residual         (project)
// grid: (ceil(HW/128), M/96, B), block: 256 (8 warps = 2m x 4n; warp tile 48x32)
template <int MODE>
__global__ __launch_bounds__(256)
void gemm_tc(const float* __restrict__ W,
             const float* __restrict__ bias,
             const float* __restrict__ in,
             float* __restrict__ out,
             int M, int K,
             const float* __restrict__ p0,   // MODE1: ln_w, MODE2: gamma
             const float* __restrict__ p1,   // MODE1: ln_b, MODE2: beta
             const float* __restrict__ resid) {
    extern __shared__ float smem[];
    float* AfB = smem;                      // [2][AF_SZ]  A[m][k], pitch 36
    float* BfB = smem + 2 * AF_SZ;          // [2][BF_SZ]  B[k][n], pitch 136
    __shared__ double s_red[16];

    const int n0 = blockIdx.x * 128;
    const int m0 = blockIdx.y * 96;
    const int b  = blockIdx.z;
    const int tid  = threadIdx.x;
    const int lane = tid & 31;
    const int warp = tid >> 5;
    const int warp_m = warp >> 2;    // 0..1
    const int warp_n = warp & 3;     // 0..3

    const float* inb = in + (size_t)b * K * HWP;
    const float inv_sum = (MODE == 2) ? (1.0f / g_svsum) : 0.0f;

    float mu = 0.0f, rs = 0.0f;
    if (MODE == 1) {
        double m_ = g_red[b * 2 + 0] / (double)CHW;
        double v_ = g_red[b * 2 + 1] / (double)CHW - m_ * m_;
        mu = (float)m_;
        rs = (float)(1.0 / sqrt(v_ + 1e-6));
    }

    float acc[3][4][4];
    #pragma unroll
    for (int mt = 0; mt < 3; mt++)
        #pragma unroll
        for (int nt = 0; nt < 4; nt++)
            #pragma unroll
            for (int j = 0; j < 4; j++) acc[mt][nt][j] = 0.0f;

    const int NK = K >> 5;
    float4 rA[3], rB[4];

    // ---- load tile k0 into registers ----
    auto load_tile = [&](int k0) {
        #pragma unroll
        for (int u = 0; u < 3; u++) {
            int i = tid + u * 256;
            int m = i >> 3, q = i & 7;
            rA[u] = *reinterpret_cast<const float4*>(&W[(size_t)(m0 + m) * K + k0 + q * 4]);
        }
        #pragma unroll
        for (int u = 0; u < 4; u++) {
            int i = tid + u * 256;
            int kk = i >> 5, nq = i & 31;
            int gn = n0 + nq * 4;
            rB[u] = (gn < HWP)
                  ? *reinterpret_cast<const float4*>(&inb[(size_t)(k0 + kk) * HWP + gn])
                  : make_float4(0.f, 0.f, 0.f, 0.f);
        }
    };

    // ---- store registers into natural-major smem stage (cvt + transforms, STS.128) ----
    auto store_tile = [&](int k0, int stage) {
        float* Af = AfB + stage * AF_SZ;
        float* Bf = BfB + stage * BF_SZ;
        #pragma unroll
        for (int u = 0; u < 3; u++) {
            int i = tid + u * 256;
            int m = i >> 3, q = i & 7;
            *reinterpret_cast<float4*>(&Af[m * A_PITCH + q * 4]) = tf32r4(rA[u]);
        }
        #pragma unroll
        for (int u = 0; u < 4; u++) {
            int i = tid + u * 256;
            int kk = i >> 5, nq = i & 31;
            int gn = n0 + nq * 4;
            float4 v = rB[u];
            if (MODE == 1) {
                if (gn < HWP) {
                    size_t li = (size_t)(k0 + kk) * HWP + gn;
                    float4 lw = *reinterpret_cast<const float4*>(&p0[li]);
                    float4 lb = *reinterpret_cast<const float4*>(&p1[li]);
                    v.x = fmaf((v.x - mu) * rs, lw.x, lb.x);
                    v.y = fmaf((v.y - mu) * rs, lw.y, lb.y);
                    v.z = fmaf((v.z - mu) * rs, lw.z, lb.z);
                    v.w = fmaf((v.w - mu) * rs, lw.w, lb.w);
                }
            }
            if (MODE == 2) {
                int idx = b * C4 + k0 + kk;
                float s  = fmaf(p0[idx] * g_sv[idx], inv_sum, 1.0f);
                float sh = p1[idx];
                v.x = fmaf(v.x, s, sh);
                v.y = fmaf(v.y, s, sh);
                v.z = fmaf(v.z, s, sh);
                v.w = fmaf(v.w, s, sh);
            }
            *reinterpret_cast<float4*>(&Bf[kk * B_PITCH + nq * 4]) = tf32r4(v);
        }
    };

    auto compute = [&](int stage) {
        const float* Af = AfB + stage * AF_SZ;
        const float* Bf = BfB + stage * BF_SZ;
        const int mbase = warp_m * 48 + (lane >> 2);     // + mt*16 (+8)
        const int nbase = warp_n * 32 + (lane >> 2);     // + nt*8
        #pragma unroll
        for (int ks = 0; ks < 4; ks++) {
            const int kq = ks * 8 + (lane & 3);
            const float* Ak = Af + kq;                    // A[m][kq]
            const float* Bk = Bf + kq * B_PITCH;          // B[kq][n]
            float4 afr[3];
            #pragma unroll
            for (int mt = 0; mt < 3; mt++) {
                const int mrow = (mbase + mt * 16) * A_PITCH;
                afr[mt].x = Ak[mrow];
                afr[mt].y = Ak[mrow + 8 * A_PITCH];
                afr[mt].z = Ak[mrow + 4];
                afr[mt].w = Ak[mrow + 8 * A_PITCH + 4];
            }
            float2 bfr[4];
            #pragma unroll
            for (int nt = 0; nt < 4; nt++) {
                const int nc = nbase + nt * 8;
                bfr[nt].x = Bk[nc];
                bfr[nt].y = Bk[4 * B_PITCH + nc];
            }
            #pragma unroll
            for (int mt = 0; mt < 3; mt++)
                #pragma unroll
                for (int nt = 0; nt < 4; nt++)
                    mma_tf32(acc[mt][nt],
                             reinterpret_cast<const unsigned*>(&afr[mt]),
                             reinterpret_cast<const unsigned*>(&bfr[nt]));
        }
    };

    // prologue: stage 0
    load_tile(0);
    store_tile(0, 0);
    __syncthreads();

    for (int it = 0; it < NK; it++) {
        const int stage = it & 1;
        if (it + 1 < NK) {
            load_tile((it + 1) << 5);   // LDG in flight during compute
            compute(stage);
            store_tile((it + 1) << 5, stage ^ 1);
        } else {
            compute(stage);
        }
        __syncthreads();
    }

    // ---- epilogue ----
    float f1 = 0.0f, f2 = 0.0f;     // fp32 per-thread LN partials (24 values)
    #pragma unroll
    for (int mt = 0; mt < 3; mt++) {
        const int mA = m0 + warp_m * 48 + mt * 16 + (lane >> 2);
        const float biasA = bias[mA];
        const float biasB = bias[mA + 8];
        #pragma unroll
        for (int nt = 0; nt < 4; nt++) {
            const int n = n0 + warp_n * 32 + nt * 8 + 2 * (lane & 3);
            if (n < HWP) {
                #pragma unroll
                for (int rr = 0; rr < 2; rr++) {
                    const int mm = mA + rr * 8;
                    float v0 = acc[mt][nt][rr * 2 + 0] + (rr ? biasB : biasA);
                    float v1 = acc[mt][nt][rr * 2 + 1] + (rr ? biasB : biasA);
                    if (MODE == 1) { v0 = gelu_tanh_f(v0); v1 = gelu_tanh_f(v1); }
                    const size_t o = ((size_t)b * M + mm) * HWP + n;
                    if (MODE == 2) {
                        float2 r2 = *reinterpret_cast<const float2*>(&resid[o]);
                        v0 += r2.x; v1 += r2.y;
                    }
                    *reinterpret_cast<float2*>(&out[o]) = make_float2(v0, v1);
                    if (MODE == 0) {
                        f1 += v0 + v1;
                        f2 += v0 * v0 + v1 * v1;
                    }
                }
            }
        }
    }

    if (MODE == 0) {
        double s1 = (double)f1, s2 = (double)f2;
        #pragma unroll
        for (int off = 16; off > 0; off >>= 1) {
            s1 += __shfl_down_sync(0xffffffff, s1, off);
            s2 += __shfl_down_sync(0xffffffff, s2, off);
        }
        if (lane == 0) { s_red[warp] = s1; s_red[8 + warp] = s2; }
        __syncthreads();
        if (warp == 0) {
            double a1 = (lane < 8) ? s_red[lane] : 0.0;
            double a2 = (lane < 8) ? s_red[8 + lane] : 0.0;
            #pragma unroll
            for (int off = 4; off > 0; off >>= 1) {
                a1 += __shfl_down_sync(0xffffffff, a1, off);
                a2 += __shfl_down_sync(0xffffffff, a2, off);
            }
            if (lane == 0) {
                atomicAdd(&g_red[b * 2 + 0], a1);
                atomicAdd(&g_red[b * 2 + 1], a2);
            }
        }
    }
}

// ---------------- sv estimate: streaming row sums, no smem tile ----------------
// sigma ~= ||A v0|| = ||rowsums|| / sqrt(56), v0 = uniform unit vector.
// grid: B*C4 = 6144, block: 128. 2 threads per row, 7 coalesced float4 each.
// All shuffles unconditional (hang-safe).
__global__ void sv_rowsum_kernel() {
    __shared__ float srow[56];

    const int bc = blockIdx.x;
    const int t  = threadIdx.x;
    const float* src = g_buf3 + (size_t)bc * HWP;

    const int r     = t >> 1;            // logical row 0..63
    const int h     = t & 1;             // half: 28 elements (112B-aligned)
    const bool valid = (r < 56);
    const int rc    = valid ? r : 0;     // clamped in-bounds row

    // half-row sum straight from global (coalesced float4 stream)
    {
        const float4* p = reinterpret_cast<const float4*>(src + rc * 56 + h * 28);
        float s = 0.0f;
        #pragma unroll
        for (int j = 0; j < 7; j++) {
            float4 a = p[j];
            s += a.x + a.y + a.z + a.w;
        }
        s += __shfl_xor_sync(0xffffffff, s, 1);
        if (valid && h == 0) srow[r] = s;
    }
    __syncthreads();

    // sigma = ||rowsums|| / sqrt(56)
    if (t < 32) {
        float a  = srow[t];
        float b2 = (t < 24) ? srow[t + 32] : 0.0f;
        float p = a * a + b2 * b2;
        #pragma unroll
        for (int off = 16; off > 0; off >>= 1)
            p += __shfl_xor_sync(0xffffffff, p, off);
        if (t == 0) {
            float sigma = sqrtf(p) * 0.1336306f;   // * 1/sqrt(56)
            g_sv[bc] = sigma;
            atomicAdd(&g_svsum, sigma);
        }
    }
}

// ---------------- launch ----------------
extern "C" void kernel_launch(void* const* d_in, const int* in_sizes, int n_in,
                              void* d_out, int out_size) {
    const float* x     = (const float*)d_in[0];
    const float* dw_w  = (const float*)d_in[1];
    const float* dw_b  = (const float*)d_in[2];
    const float* pw_w  = (const float*)d_in[3];
    const float* pw_b  = (const float*)d_in[4];
    const float* ln_w  = (const float*)d_in[5];
    const float* ln_b  = (const float*)d_in[6];
    const float* l1_w  = (const float*)d_in[7];
    const float* l1_b  = (const float*)d_in[8];
    const float* gamma = (const float*)d_in[9];
    const float* beta  = (const float*)d_in[10];
    const float* l2_w  = (const float*)d_in[11];
    const float* l2_b  = (const float*)d_in[12];
    float* out = (float*)d_out;

    float* buf1; cudaGetSymbolAddress((void**)&buf1, g_buf1);
    float* buf2; cudaGetSymbolAddress((void**)&buf2, g_buf2);
    float* buf3; cudaGetSymbolAddress((void**)&buf3, g_buf3);

    // raise dynamic smem limit (idempotent host-side attribute set)
    cudaFuncSetAttribute(gemm_tc<0>, cudaFuncAttributeMaxDynamicSharedMemorySize, SMEM_DYN);
    cudaFuncSetAttribute(gemm_tc<1>, cudaFuncAttributeMaxDynamicSharedMemorySize, SMEM_DYN);
    cudaFuncSetAttribute(gemm_tc<2>, cudaFuncAttributeMaxDynamicSharedMemorySize, SMEM_DYN);

    const int NB = (HWP + 127) / 128;   // 25

    // 1) depthwise conv -> buf1 (+ zero-init of reductions)
    dw_conv_kernel<<<dim3(1, 7, BB * CC), dim3(56, 8)>>>(x, dw_w, dw_b);

    // 2) pointwise 96->96 -> buf2 (+ fused LN stats)
    gemm_tc<0><<<dim3(NB, 1, BB), 256, SMEM_DYN>>>(pw_w, pw_b, buf1, buf2, CC, CC,
                                                   nullptr, nullptr, nullptr);

    // 3) expand 96->384 with fused LN on input + GELU -> buf3
    gemm_tc<1><<<dim3(NB, C4 / 96, BB), 256, SMEM_DYN>>>(l1_w, l1_b, buf2, buf3, C4, CC,
                                                         ln_w, ln_b, nullptr);

    // 4) sv estimates: streaming row-sum norm (replaces power iteration)
    sv_rowsum_kernel<<<BB * C4, 128>>>();

    // 5) GRN affine + project 384->96 + bias + residual -> out
    gemm_tc<2><<<dim3(NB, 1, BB), 256, SMEM_DYN>>>(l2_w, l2_b, buf3, out, CC, C4,
                                                   gamma, beta, x);
}

// round 12
// speedup vs baseline: 1.0036x; 1.0036x over previous
#include <cuda_runtime.h>
#include <math.h>

#define BB   16
#define CC   96
#define C4   384
#define HH   56
#define WW   56
#define HWP  3136          // 56*56
#define CHW  301056        // 96*3136

// fragment-tile sizes (floats)
#define AF_SZ  (4 * 6 * 33 * 4)    // 3168
#define BF_SZ  (4 * 16 * 33 * 2)   // 4224
#define SMEM_DYN ((2 * (AF_SZ + BF_SZ)) * 4)   // 59136 bytes

// ---------------- scratch (device globals; no allocation) ----------------
__device__ float  g_buf1[BB * CC * HWP];   // dw out
__device__ float  g_buf2[BB * CC * HWP];   // pw out (pre-LN)
__device__ float  g_buf3[BB * C4 * HWP];   // expand+gelu out
__device__ double g_red[BB * 2];           // LN sum / sumsq per batch
__device__ float  g_rowsum[BB * C4 * 56];  // per-slice HW-row sums (from gemm1)
__device__ float  g_sv[BB * C4];           // top-singular-value estimates
__device__ float  g_svsum;                 // sum of all sv

// ---------------- helpers ----------------
__device__ __forceinline__ float gelu_tanh_f(float x) {
    const float c = 0.7978845608028654f;
    float x3 = x * x * x;
    return 0.5f * x * (1.0f + tanhf(c * (x + 0.044715f * x3)));
}

__device__ __forceinline__ float tf32r(float x) {
    unsigned u;
    asm("cvt.rna.tf32.f32 %0, %1;" : "=r"(u) : "f"(x));
    return __uint_as_float(u);
}

__device__ __forceinline__ void mma_tf32(float* c, const unsigned* a, const unsigned* b2) {
    asm volatile("mma.sync.aligned.m16n8k8.row.col.f32.tf32.tf32.f32 "
        "{%0,%1,%2,%3}, {%4,%5,%6,%7}, {%8,%9}, {%0,%1,%2,%3};"
        : "+f"(c[0]), "+f"(c[1]), "+f"(c[2]), "+f"(c[3])
        : "r"(a[0]), "r"(a[1]), "r"(a[2]), "r"(a[3]), "r"(b2[0]), "r"(b2[1]));
}

// ---------------- 1) depthwise 7x7 conv + bias (+ scratch zero-init) ----------------
__global__ void dw_conv_kernel(const float* __restrict__ x,
                               const float* __restrict__ dw_w,
                               const float* __restrict__ dw_b) {
    __shared__ float tile[14][62];
    __shared__ float sw[49];

    const int bc = blockIdx.z;
    const int c  = bc % CC;
    const int y0 = blockIdx.y * 8;
    const int tx = threadIdx.x;
    const int ty = threadIdx.y;
    const int tid = ty * 56 + tx;

    if (bc == 0 && blockIdx.y == 0) {
        if (tid < BB * 2) g_red[tid] = 0.0;
        if (tid == BB * 2) g_svsum = 0.0f;
    }
    // zero g_rowsum: 10752 blocks x 32 floats = 344064 = BB*C4*56 exactly
    {
        const int blk = bc * 7 + blockIdx.y;
        if (tid < 32) g_rowsum[blk * 32 + tid] = 0.0f;
    }

    const float* src = x + (size_t)bc * HWP;
    if (tid < 49) sw[tid] = dw_w[c * 49 + tid];

    for (int i = tid; i < 14 * 62; i += 448) {
        int r  = i / 62;
        int cx = i - r * 62;
        int gy = y0 - 3 + r;
        int gx = cx - 3;
        float v = 0.0f;
        if (gy >= 0 && gy < HH && gx >= 0 && gx < WW) v = src[gy * WW + gx];
        tile[r][cx] = v;
    }
    __syncthreads();

    float acc = dw_b[c];
    #pragma unroll
    for (int dy = 0; dy < 7; dy++)
        #pragma unroll
        for (int dx = 0; dx < 7; dx++)
            acc = fmaf(sw[dy * 7 + dx], tile[ty + dy][tx + dx], acc);

    g_buf1[(size_t)bc * HWP + (y0 + ty) * WW + tx] = acc;
}

// ---------------- TF32 TC GEMM, fragment-order smem, double-buffered, 1 sync/iter ----------------
// out[b,m,n] = sum_k W[m,k]*in[b,k,n]
// MODE 0: +bias, fused LN sum/sumsq reduction             (pointwise)
// MODE 1: LN applied to B at staging, +bias, gelu,
//         fused shuffle-based HW-row-sum reduction        (expand)
// MODE 2: B scaled by GRN affine, +bias, +residual         (project)
// grid: (ceil(HW/128), M/96, B), block: 256 (8 warps = 2m x 4n; warp tile 48x32)
template <int MODE>
__global__ __launch_bounds__(256)
void gemm_tc(const float* __restrict__ W,
             const float* __restrict__ bias,
             const float* __restrict__ in,
             float* __restrict__ out,
             int M, int K,
             const float* __restrict__ p0,   // MODE1: ln_w, MODE2: gamma
             const float* __restrict__ p1,   // MODE1: ln_b, MODE2: beta
             const float* __restrict__ resid) {
    extern __shared__ float smem[];
    float* AfB = smem;                      // [2][AF_SZ]
    float* BfB = smem + 2 * AF_SZ;          // [2][BF_SZ]
    __shared__ double s_red[16];
    __shared__ float srow[96][4][5];        // MODE1: [m][row-local][warp_n], pad->stride 20

    const int n0 = blockIdx.x * 128;
    const int m0 = blockIdx.y * 96;
    const int b  = blockIdx.z;
    const int tid  = threadIdx.x;
    const int lane = tid & 31;
    const int warp = tid >> 5;
    const int warp_m = warp >> 2;    // 0..1
    const int warp_n = warp & 3;     // 0..3
    const int row0 = n0 / 56;        // first HW-row touched (local rows 0..3)

    const float* inb = in + (size_t)b * K * HWP;
    const float inv_sum = (MODE == 2) ? (1.0f / g_svsum) : 0.0f;

    float mu = 0.0f, rs = 0.0f;
    if (MODE == 1) {
        double m_ = g_red[b * 2 + 0] / (double)CHW;
        double v_ = g_red[b * 2 + 1] / (double)CHW - m_ * m_;
        mu = (float)m_;
        rs = (float)(1.0 / sqrt(v_ + 1e-6));
    }

    float acc[3][4][4];
    #pragma unroll
    for (int mt = 0; mt < 3; mt++)
        #pragma unroll
        for (int nt = 0; nt < 4; nt++)
            #pragma unroll
            for (int j = 0; j < 4; j++) acc[mt][nt][j] = 0.0f;

    const int NK = K >> 5;
    float4 rA[3], rB[4];

    // ---- load tile k0 into registers ----
    auto load_tile = [&](int k0) {
        #pragma unroll
        for (int u = 0; u < 3; u++) {
            int i = tid + u * 256;
            int m = i >> 3, q = i & 7;
            rA[u] = *reinterpret_cast<const float4*>(&W[(size_t)(m0 + m) * K + k0 + q * 4]);
        }
        #pragma unroll
        for (int u = 0; u < 4; u++) {
            int i = tid + u * 256;
            int kk = i >> 5, nq = i & 31;
            int gn = n0 + nq * 4;
            rB[u] = (gn < HWP)
                  ? *reinterpret_cast<const float4*>(&inb[(size_t)(k0 + kk) * HWP + gn])
                  : make_float4(0.f, 0.f, 0.f, 0.f);
        }
    };

    // ---- store registers into fragment-order smem stage (with cvt + transforms) ----
    auto store_tile = [&](int k0, int stage) {
        float* Af = AfB + stage * AF_SZ;
        float* Bf = BfB + stage * BF_SZ;
        #pragma unroll
        for (int u = 0; u < 3; u++) {
            int i = tid + u * 256;
            int m = i >> 3, q = i & 7;
            int ks = q >> 1;
            int mt = m >> 4;
            int g  = m & 7;
            int rp = ((q & 1) << 1) | ((m >> 3) & 1);
            float* dst = &Af[((ks * 6 + mt) * 33 + g * 4) * 4 + rp];
            dst[0]  = tf32r(rA[u].x);
            dst[4]  = tf32r(rA[u].y);
            dst[8]  = tf32r(rA[u].z);
            dst[12] = tf32r(rA[u].w);
        }
        #pragma unroll
        for (int u = 0; u < 4; u++) {
            int i = tid + u * 256;
            int kk = i >> 5, nq = i & 31;
            int gn = n0 + nq * 4;
            float4 v = rB[u];
            if (MODE == 1) {
                if (gn < HWP) {
                    size_t li = (size_t)(k0 + kk) * HWP + gn;
                    float4 lw = *reinterpret_cast<const float4*>(&p0[li]);
                    float4 lb = *reinterpret_cast<const float4*>(&p1[li]);
                    v.x = fmaf((v.x - mu) * rs, lw.x, lb.x);
                    v.y = fmaf((v.y - mu) * rs, lw.y, lb.y);
                    v.z = fmaf((v.z - mu) * rs, lw.z, lb.z);
                    v.w = fmaf((v.w - mu) * rs, lw.w, lb.w);
                }
            }
            if (MODE == 2) {
                int idx = b * C4 + k0 + kk;
                float s  = fmaf(p0[idx] * g_sv[idx], inv_sum, 1.0f);
                float sh = p1[idx];
                v.x = fmaf(v.x, s, sh);
                v.y = fmaf(v.y, s, sh);
                v.z = fmaf(v.z, s, sh);
                v.w = fmaf(v.w, s, sh);
            }
            int ks  = kk >> 3, kin = kk & 7;
            int nt  = nq >> 1;
            float* dst = &Bf[((ks * 16 + nt) * 33 + ((nq & 1) << 4) + (kin & 3)) * 2 + (kin >> 2)];
            dst[0]  = tf32r(v.x);
            dst[8]  = tf32r(v.y);
            dst[16] = tf32r(v.z);
            dst[24] = tf32r(v.w);
        }
    };

    auto compute = [&](int stage) {
        const float* Af = AfB + stage * AF_SZ;
        const float* Bf = BfB + stage * BF_SZ;
        #pragma unroll
        for (int ks = 0; ks < 4; ks++) {
            float4 afr[3];
            #pragma unroll
            for (int mt = 0; mt < 3; mt++)
                afr[mt] = *reinterpret_cast<const float4*>(
                    &Af[((ks * 6 + warp_m * 3 + mt) * 33 + lane) * 4]);
            float2 bfr[4];
            #pragma unroll
            for (int nt = 0; nt < 4; nt++)
                bfr[nt] = *reinterpret_cast<const float2*>(
                    &Bf[((ks * 16 + warp_n * 4 + nt) * 33 + lane) * 2]);
            #pragma unroll
            for (int mt = 0; mt < 3; mt++)
                #pragma unroll
                for (int nt = 0; nt < 4; nt++)
                    mma_tf32(acc[mt][nt],
                             reinterpret_cast<const unsigned*>(&afr[mt]),
                             reinterpret_cast<const unsigned*>(&bfr[nt]));
        }
    };

    // prologue: stage 0
    load_tile(0);
    store_tile(0, 0);
    __syncthreads();

    for (int it = 0; it < NK; it++) {
        const int stage = it & 1;
        if (it + 1 < NK) {
            load_tile((it + 1) << 5);   // LDG in flight during compute
            compute(stage);
            store_tile((it + 1) << 5, stage ^ 1);
        } else {
            compute(stage);
        }
        __syncthreads();
    }

    // ---- epilogue ----
    // MODE1: precompute row-local index per nt (n and n+1 share a row; n even)
    int rln[4] = {0, 0, 0, 0};
    if (MODE == 1) {
        #pragma unroll
        for (int nt = 0; nt < 4; nt++)
            rln[nt] = (n0 + warp_n * 32 + nt * 8 + 2 * (lane & 3)) / 56 - row0;  // 0..3
    }

    float f1 = 0.0f, f2 = 0.0f;     // fp32 per-thread LN partials (24 values)
    #pragma unroll
    for (int mt = 0; mt < 3; mt++) {
        const int mA = m0 + warp_m * 48 + mt * 16 + (lane >> 2);
        const float biasA = bias[mA];
        const float biasB = bias[mA + 8];
        float racc[2][4] = {{0.f, 0.f, 0.f, 0.f}, {0.f, 0.f, 0.f, 0.f}};
        #pragma unroll
        for (int nt = 0; nt < 4; nt++) {
            const int n = n0 + warp_n * 32 + nt * 8 + 2 * (lane & 3);
            if (n < HWP) {
                #pragma unroll
                for (int rr = 0; rr < 2; rr++) {
                    const int mm = mA + rr * 8;
                    float v0 = acc[mt][nt][rr * 2 + 0] + (rr ? biasB : biasA);
                    float v1 = acc[mt][nt][rr * 2 + 1] + (rr ? biasB : biasA);
                    if (MODE == 1) { v0 = gelu_tanh_f(v0); v1 = gelu_tanh_f(v1); }
                    const size_t o = ((size_t)b * M + mm) * HWP + n;
                    if (MODE == 2) {
                        float2 r2 = *reinterpret_cast<const float2*>(&resid[o]);
                        v0 += r2.x; v1 += r2.y;
                    }
                    *reinterpret_cast<float2*>(&out[o]) = make_float2(v0, v1);
                    if (MODE == 0) {
                        f1 += v0 + v1;
                        f2 += v0 * v0 + v1 * v1;
                    }
                    if (MODE == 1) {
                        const float t = v0 + v1;
                        const int r = rln[nt];
                        racc[rr][0] += (r == 0) ? t : 0.0f;
                        racc[rr][1] += (r == 1) ? t : 0.0f;
                        racc[rr][2] += (r == 2) ? t : 0.0f;
                        racc[rr][3] += (r == 3) ? t : 0.0f;
                    }
                }
            }
        }
        if (MODE == 1) {
            // all lanes execute shuffles (convergent); only lane&3==0 stores
            #pragma unroll
            for (int rr = 0; rr < 2; rr++)
                #pragma unroll
                for (int q = 0; q < 4; q++) {
                    float s = racc[rr][q];
                    s += __shfl_xor_sync(0xffffffff, s, 1);
                    s += __shfl_xor_sync(0xffffffff, s, 2);
                    if ((lane & 3) == 0) {
                        int mloc = warp_m * 48 + mt * 16 + (lane >> 2) + rr * 8;
                        srow[mloc][q][warp_n] = s;
                    }
                }
        }
    }

    if (MODE == 0) {
        double s1 = (double)f1, s2 = (double)f2;
        #pragma unroll
        for (int off = 16; off > 0; off >>= 1) {
            s1 += __shfl_down_sync(0xffffffff, s1, off);
            s2 += __shfl_down_sync(0xffffffff, s2, off);
        }
        if (lane == 0) { s_red[warp] = s1; s_red[8 + warp] = s2; }
        __syncthreads();
        if (warp == 0) {
            double a1 = (lane < 8) ? s_red[lane] : 0.0;
            double a2 = (lane < 8) ? s_red[8 + lane] : 0.0;
            #pragma unroll
            for (int off = 4; off > 0; off >>= 1) {
                a1 += __shfl_down_sync(0xffffffff, a1, off);
                a2 += __shfl_down_sync(0xffffffff, a2, off);
            }
            if (lane == 0) {
                atomicAdd(&g_red[b * 2 + 0], a1);
                atomicAdd(&g_red[b * 2 + 1], a2);
            }
        }
    }

    if (MODE == 1) {
        __syncthreads();
        for (int i = tid; i < 96 * 4; i += 256) {
            int m = i >> 2, q = i & 3;
            int row = row0 + q;
            float s = srow[m][q][0] + srow[m][q][1] + srow[m][q][2] + srow[m][q][3];
            if (row < 56 && s != 0.0f)
                atomicAdd(&g_rowsum[((size_t)b * C4 + m0 + m) * 56 + row], s);
        }
    }
}

// ---------------- sv estimate: sigma ~= ||rowsums|| / sqrt(56) ----------------
// grid: 768 blocks x 256 (one warp per (b,c4) slice)
__global__ void sv_kernel() {
    __shared__ float s_part[8];
    const int lane = threadIdx.x & 31;
    const int warp = threadIdx.x >> 5;
    const int bc = blockIdx.x * 8 + warp;

    const float* rsum = &g_rowsum[(size_t)bc * 56];
    float a = rsum[lane];
    float bvl = (lane < 24) ? rsum[lane + 32] : 0.0f;
    float p = a * a + bvl * bvl;
    #pragma unroll
    for (int off = 16; off > 0; off >>= 1)
        p += __shfl_xor_sync(0xffffffff, p, off);

    if (lane == 0) {
        float sigma = sqrtf(p) * 0.1336306f;   // * 1/sqrt(56)
        g_sv[bc] = sigma;
        s_part[warp] = sigma;
    }
    __syncthreads();
    if (threadIdx.x == 0) {
        float s = 0.0f;
        #pragma unroll
        for (int w = 0; w < 8; w++) s += s_part[w];
        atomicAdd(&g_svsum, s);
    }
}

// ---------------- launch ----------------
extern "C" void kernel_launch(void* const* d_in, const int* in_sizes, int n_in,
                              void* d_out, int out_size) {
    const float* x     = (const float*)d_in[0];
    const float* dw_w  = (const float*)d_in[1];
    const float* dw_b  = (const float*)d_in[2];
    const float* pw_w  = (const float*)d_in[3];
    const float* pw_b  = (const float*)d_in[4];
    const float* ln_w  = (const float*)d_in[5];
    const float* ln_b  = (const float*)d_in[6];
    const float* l1_w  = (const float*)d_in[7];
    const float* l1_b  = (const float*)d_in[8];
    const float* gamma = (const float*)d_in[9];
    const float* beta  = (const float*)d_in[10];
    const float* l2_w  = (const float*)d_in[11];
    const float* l2_b  = (const float*)d_in[12];
    float* out = (float*)d_out;

    float* buf1; cudaGetSymbolAddress((void**)&buf1, g_buf1);
    float* buf2; cudaGetSymbolAddress((void**)&buf2, g_buf2);
    float* buf3; cudaGetSymbolAddress((void**)&buf3, g_buf3);

    // raise dynamic smem limit (idempotent host-side attribute set)
    cudaFuncSetAttribute(gemm_tc<0>, cudaFuncAttributeMaxDynamicSharedMemorySize, SMEM_DYN);
    cudaFuncSetAttribute(gemm_tc<1>, cudaFuncAttributeMaxDynamicSharedMemorySize, SMEM_DYN);
    cudaFuncSetAttribute(gemm_tc<2>, cudaFuncAttributeMaxDynamicSharedMemorySize, SMEM_DYN);

    const int NB = (HWP + 127) / 128;   // 25

    // 1) depthwise conv -> buf1 (+ zero-init of reductions/rowsums)
    dw_conv_kernel<<<dim3(1, 7, BB * CC), dim3(56, 8)>>>(x, dw_w, dw_b);

    // 2) pointwise 96->96 -> buf2 (+ fused LN stats)
    gemm_tc<0><<<dim3(NB, 1, BB), 256, SMEM_DYN>>>(pw_w, pw_b, buf1, buf2, CC, CC,
                                                   nullptr, nullptr, nullptr);

    // 3) expand 96->384 with fused LN + GELU + row-sum reduction -> buf3
    gemm_tc<1><<<dim3(NB, C4 / 96, BB), 256, SMEM_DYN>>>(l1_w, l1_b, buf2, buf3, C4, CC,
                                                         ln_w, ln_b, nullptr);

    // 4) sv estimates from fused row sums (no extra pass over buf3)
    sv_kernel<<<BB * C4 / 8, 256>>>();

    // 5) GRN affine + project 384->96 + bias + residual -> out
    gemm_tc<2><<<dim3(NB, 1, BB), 256, SMEM_DYN>>>(l2_w, l2_b, buf3, out, CC, C4,
                                                   gamma, beta, x);
}

// round 14
// speedup vs baseline: 1.0582x; 1.0544x over previous
#include <cuda_runtime.h>
#include <cuda_fp16.h>
#include <math.h>

#define BB   16
#define CC   96
#define C4   384
#define HH   56
#define WW   56
#define HWP  3136          // 56*56
#define CHW  301056        // 96*3136

// fragment-tile sizes (floats)
#define AF_SZ  (4 * 6 * 33 * 4)    // 3168
#define BF_SZ  (4 * 16 * 33 * 2)   // 4224
#define SMEM_DYN ((2 * (AF_SZ + BF_SZ)) * 4)   // 59136 bytes

// ---------------- scratch (device globals; no allocation) ----------------
__device__ __half g_buf1[BB * CC * HWP];   // dw out (fp16)
__device__ __half g_buf2[BB * CC * HWP];   // pw out, pre-LN (fp16)
__device__ __half g_buf3[BB * C4 * HWP];   // expand+gelu out (fp16)
__device__ double g_red[BB * 2];           // LN sum / sumsq per batch
__device__ float  g_sv[BB * C4];           // top-singular-value estimates
__device__ float  g_svsum;                 // sum of all sv

// ---------------- helpers ----------------
__device__ __forceinline__ float gelu_tanh_f(float x) {
    const float c = 0.7978845608028654f;
    float x3 = x * x * x;
    return 0.5f * x * (1.0f + tanhf(c * (x + 0.044715f * x3)));
}

__device__ __forceinline__ float tf32r(float x) {
    unsigned u;
    asm("cvt.rna.tf32.f32 %0, %1;" : "=r"(u) : "f"(x));
    return __uint_as_float(u);
}

__device__ __forceinline__ void mma_tf32(float* c, const unsigned* a, const unsigned* b2) {
    asm volatile("mma.sync.aligned.m16n8k8.row.col.f32.tf32.tf32.f32 "
        "{%0,%1,%2,%3}, {%4,%5,%6,%7}, {%8,%9}, {%0,%1,%2,%3};"
        : "+f"(c[0]), "+f"(c[1]), "+f"(c[2]), "+f"(c[3])
        : "r"(a[0]), "r"(a[1]), "r"(a[2]), "r"(a[3]), "r"(b2[0]), "r"(b2[1]));
}

// ---------------- 1) depthwise 7x7 conv + bias (+ scratch zero-init) ----------------
__global__ void dw_conv_kernel(const float* __restrict__ x,
                               const float* __restrict__ dw_w,
                               const float* __restrict__ dw_b) {
    __shared__ float tile[14][62];
    __shared__ float sw[49];

    const int bc = blockIdx.z;
    const int c  = bc % CC;
    const int y0 = blockIdx.y * 8;
    const int tx = threadIdx.x;
    const int ty = threadIdx.y;
    const int tid = ty * 56 + tx;

    if (bc == 0 && blockIdx.y == 0) {
        if (tid < BB * 2) g_red[tid] = 0.0;
        if (tid == BB * 2) g_svsum = 0.0f;
    }

    const float* src = x + (size_t)bc * HWP;
    if (tid < 49) sw[tid] = dw_w[c * 49 + tid];

    for (int i = tid; i < 14 * 62; i += 448) {
        int r  = i / 62;
        int cx = i - r * 62;
        int gy = y0 - 3 + r;
        int gx = cx - 3;
        float v = 0.0f;
        if (gy >= 0 && gy < HH && gx >= 0 && gx < WW) v = src[gy * WW + gx];
        tile[r][cx] = v;
    }
    __syncthreads();

    float acc = dw_b[c];
    #pragma unroll
    for (int dy = 0; dy < 7; dy++)
        #pragma unroll
        for (int dx = 0; dx < 7; dx++)
            acc = fmaf(sw[dy * 7 + dx], tile[ty + dy][tx + dx], acc);

    g_buf1[(size_t)bc * HWP + (y0 + ty) * WW + tx] = __float2half(acc);
}

// ---------------- TF32 TC GEMM, fragment-order smem, double-buffered, fp16 B input ----------------
// out[b,m,n] = sum_k W[m,k]*in[b,k,n]
// MODE 0: +bias, fused LN sum/sumsq reduction, fp16 out    (pointwise)
// MODE 1: LN applied to B at staging, +bias, gelu, fp16 out (expand)
// MODE 2: B scaled by GRN affine, +bias, +residual, f32 out (project)
// grid: (ceil(HW/128), M/96, B), block: 256 (8 warps = 2m x 4n; warp tile 48x32)
template <int MODE>
__global__ __launch_bounds__(256)
void gemm_tc(const float* __restrict__ W,
             const float* __restrict__ bias,
             const __half* __restrict__ in,
             void* __restrict__ outv,
             int M, int K,
             const float* __restrict__ p0,   // MODE1: ln_w, MODE2: gamma
             const float* __restrict__ p1,   // MODE1: ln_b, MODE2: beta
             const float* __restrict__ resid) {
    extern __shared__ float smem[];
    float* AfB = smem;                      // [2][AF_SZ]
    float* BfB = smem + 2 * AF_SZ;          // [2][BF_SZ]
    __shared__ double s_red[16];

    const int n0 = blockIdx.x * 128;
    const int m0 = blockIdx.y * 96;
    const int b  = blockIdx.z;
    const int tid  = threadIdx.x;
    const int lane = tid & 31;
    const int warp = tid >> 5;
    const int warp_m = warp >> 2;    // 0..1
    const int warp_n = warp & 3;     // 0..3

    const __half* inb = in + (size_t)b * K * HWP;
    const float inv_sum = (MODE == 2) ? (1.0f / g_svsum) : 0.0f;

    float mu = 0.0f, rs = 0.0f;
    if (MODE == 1) {
        double m_ = g_red[b * 2 + 0] / (double)CHW;
        double v_ = g_red[b * 2 + 1] / (double)CHW - m_ * m_;
        mu = (float)m_;
        rs = (float)(1.0 / sqrt(v_ + 1e-6));
    }

    float acc[3][4][4];
    #pragma unroll
    for (int mt = 0; mt < 3; mt++)
        #pragma unroll
        for (int nt = 0; nt < 4; nt++)
            #pragma unroll
            for (int j = 0; j < 4; j++) acc[mt][nt][j] = 0.0f;

    const int NK = K >> 5;
    float4 rA[3];
    uint2  rB[4];   // 4 halves each

    // ---- load tile k0 into registers ----
    auto load_tile = [&](int k0) {
        #pragma unroll
        for (int u = 0; u < 3; u++) {
            int i = tid + u * 256;
            int m = i >> 3, q = i & 7;
            rA[u] = *reinterpret_cast<const float4*>(&W[(size_t)(m0 + m) * K + k0 + q * 4]);
        }
        #pragma unroll
        for (int u = 0; u < 4; u++) {
            int i = tid + u * 256;
            int kk = i >> 5, nq = i & 31;
            int gn = n0 + nq * 4;
            rB[u] = (gn < HWP)
                  ? *reinterpret_cast<const uint2*>(inb + (size_t)(k0 + kk) * HWP + gn)
                  : make_uint2(0u, 0u);
        }
    };

    // ---- store registers into fragment-order smem stage (cvt + transforms) ----
    auto store_tile = [&](int k0, int stage) {
        float* Af = AfB + stage * AF_SZ;
        float* Bf = BfB + stage * BF_SZ;
        #pragma unroll
        for (int u = 0; u < 3; u++) {
            int i = tid + u * 256;
            int m = i >> 3, q = i & 7;
            int ks = q >> 1;
            int mt = m >> 4;
            int g  = m & 7;
            int rp = ((q & 1) << 1) | ((m >> 3) & 1);
            float* dst = &Af[((ks * 6 + mt) * 33 + g * 4) * 4 + rp];
            dst[0]  = tf32r(rA[u].x);
            dst[4]  = tf32r(rA[u].y);
            dst[8]  = tf32r(rA[u].z);
            dst[12] = tf32r(rA[u].w);
        }
        #pragma unroll
        for (int u = 0; u < 4; u++) {
            int i = tid + u * 256;
            int kk = i >> 5, nq = i & 31;
            int gn = n0 + nq * 4;
            float2 f01 = __half22float2(*reinterpret_cast<const __half2*>(&rB[u].x));
            float2 f23 = __half22float2(*reinterpret_cast<const __half2*>(&rB[u].y));
            float4 v = make_float4(f01.x, f01.y, f23.x, f23.y);
            if (MODE == 1) {
                if (gn < HWP) {
                    size_t li = (size_t)(k0 + kk) * HWP + gn;
                    float4 lw = *reinterpret_cast<const float4*>(&p0[li]);
                    float4 lb = *reinterpret_cast<const float4*>(&p1[li]);
                    v.x = fmaf((v.x - mu) * rs, lw.x, lb.x);
                    v.y = fmaf((v.y - mu) * rs, lw.y, lb.y);
                    v.z = fmaf((v.z - mu) * rs, lw.z, lb.z);
                    v.w = fmaf((v.w - mu) * rs, lw.w, lb.w);
                }
            }
            if (MODE == 2) {
                int idx = b * C4 + k0 + kk;
                float s  = fmaf(p0[idx] * g_sv[idx], inv_sum, 1.0f);
                float sh = p1[idx];
                v.x = fmaf(v.x, s, sh);
                v.y = fmaf(v.y, s, sh);
                v.z = fmaf(v.z, s, sh);
                v.w = fmaf(v.w, s, sh);
            }
            int ks  = kk >> 3, kin = kk & 7;
            int nt  = nq >> 1;
            float* dst = &Bf[((ks * 16 + nt) * 33 + ((nq & 1) << 4) + (kin & 3)) * 2 + (kin >> 2)];
            if (MODE == 0) {
                // fp16-exact values are tf32-exact: no cvt needed
                dst[0]  = v.x;
                dst[8]  = v.y;
                dst[16] = v.z;
                dst[24] = v.w;
            } else {
                dst[0]  = tf32r(v.x);
                dst[8]  = tf32r(v.y);
                dst[16] = tf32r(v.z);
                dst[24] = tf32r(v.w);
            }
        }
    };

    auto compute = [&](int stage) {
        const float* Af = AfB + stage * AF_SZ;
        const float* Bf = BfB + stage * BF_SZ;
        #pragma unroll
        for (int ks = 0; ks < 4; ks++) {
            float4 afr[3];
            #pragma unroll
            for (int mt = 0; mt < 3; mt++)
                afr[mt] = *reinterpret_cast<const float4*>(
                    &Af[((ks * 6 + warp_m * 3 + mt) * 33 + lane) * 4]);
            float2 bfr[4];
            #pragma unroll
            for (int nt = 0; nt < 4; nt++)
                bfr[nt] = *reinterpret_cast<const float2*>(
                    &Bf[((ks * 16 + warp_n * 4 + nt) * 33 + lane) * 2]);
            #pragma unroll
            for (int mt = 0; mt < 3; mt++)
                #pragma unroll
                for (int nt = 0; nt < 4; nt++)
                    mma_tf32(acc[mt][nt],
                             reinterpret_cast<const unsigned*>(&afr[mt]),
                             reinterpret_cast<const unsigned*>(&bfr[nt]));
        }
    };

    // prologue: stage 0
    load_tile(0);
    store_tile(0, 0);
    __syncthreads();

    for (int it = 0; it < NK; it++) {
        const int stage = it & 1;
        if (it + 1 < NK) {
            load_tile((it + 1) << 5);   // LDG in flight during compute
            compute(stage);
            store_tile((it + 1) << 5, stage ^ 1);
        } else {
            compute(stage);
        }
        __syncthreads();
    }

    // ---- epilogue ----
    __half* outh = reinterpret_cast<__half*>(outv);
    float*  outf = reinterpret_cast<float*>(outv);

    float f1 = 0.0f, f2 = 0.0f;     // fp32 per-thread LN partials (24 values)
    #pragma unroll
    for (int mt = 0; mt < 3; mt++) {
        const int mA = m0 + warp_m * 48 + mt * 16 + (lane >> 2);
        const float biasA = bias[mA];
        const float biasB = bias[mA + 8];
        #pragma unroll
        for (int nt = 0; nt < 4; nt++) {
            const int n = n0 + warp_n * 32 + nt * 8 + 2 * (lane & 3);
            if (n < HWP) {
                #pragma unroll
                for (int rr = 0; rr < 2; rr++) {
                    const int mm = mA + rr * 8;
                    float v0 = acc[mt][nt][rr * 2 + 0] + (rr ? biasB : biasA);
                    float v1 = acc[mt][nt][rr * 2 + 1] + (rr ? biasB : biasA);
                    if (MODE == 1) { v0 = gelu_tanh_f(v0); v1 = gelu_tanh_f(v1); }
                    const size_t o = ((size_t)b * M + mm) * HWP + n;
                    if (MODE == 2) {
                        float2 r2 = *reinterpret_cast<const float2*>(&resid[o]);
                        v0 += r2.x; v1 += r2.y;
                        *reinterpret_cast<float2*>(&outf[o]) = make_float2(v0, v1);
                    } else {
                        *reinterpret_cast<__half2*>(&outh[o]) = __floats2half2_rn(v0, v1);
                    }
                    if (MODE == 0) {
                        f1 += v0 + v1;
                        f2 += v0 * v0 + v1 * v1;
                    }
                }
            }
        }
    }

    if (MODE == 0) {
        double s1 = (double)f1, s2 = (double)f2;
        #pragma unroll
        for (int off = 16; off > 0; off >>= 1) {
            s1 += __shfl_down_sync(0xffffffff, s1, off);
            s2 += __shfl_down_sync(0xffffffff, s2, off);
        }
        if (lane == 0) { s_red[warp] = s1; s_red[8 + warp] = s2; }
        __syncthreads();
        if (warp == 0) {
            double a1 = (lane < 8) ? s_red[lane] : 0.0;
            double a2 = (lane < 8) ? s_red[8 + lane] : 0.0;
            #pragma unroll
            for (int off = 4; off > 0; off >>= 1) {
                a1 += __shfl_down_sync(0xffffffff, a1, off);
                a2 += __shfl_down_sync(0xffffffff, a2, off);
            }
            if (lane == 0) {
                atomicAdd(&g_red[b * 2 + 0], a1);
                atomicAdd(&g_red[b * 2 + 1], a2);
            }
        }
    }
}

// ---------------- sv estimate: streaming fp16 row sums ----------------
// sigma ~= ||A v0|| = ||rowsums|| / sqrt(56), v0 = uniform unit vector.
// grid: B*C4 = 6144, block: 64. One thread per row: 7 x uint4 = 56 halves.
__global__ void sv_rowsum_kernel() {
    __shared__ float srow[56];

    const int bc = blockIdx.x;
    const int t  = threadIdx.x;
    const __half* src = g_buf3 + (size_t)bc * HWP;

    if (t < 56) {
        const uint4* p = reinterpret_cast<const uint4*>(src + t * 56);
        float s = 0.0f;
        #pragma unroll
        for (int j = 0; j < 7; j++) {
            uint4 q = p[j];
            float2 a = __half22float2(*reinterpret_cast<const __half2*>(&q.x));
            float2 b = __half22float2(*reinterpret_cast<const __half2*>(&q.y));
            float2 c = __half22float2(*reinterpret_cast<const __half2*>(&q.z));
            float2 d = __half22float2(*reinterpret_cast<const __half2*>(&q.w));
            s += a.x + a.y + b.x + b.y + c.x + c.y + d.x + d.y;
        }
        srow[t] = s;
    }
    __syncthreads();

    // sigma = ||rowsums|| / sqrt(56)
    if (t < 32) {
        float a  = srow[t];
        float b2 = (t < 24) ? srow[t + 32] : 0.0f;
        float p = a * a + b2 * b2;
        #pragma unroll
        for (int off = 16; off > 0; off >>= 1)
            p += __shfl_xor_sync(0xffffffff, p, off);
        if (t == 0) {
            float sigma = sqrtf(p) * 0.1336306f;   // * 1/sqrt(56)
            g_sv[bc] = sigma;
            atomicAdd(&g_svsum, sigma);
        }
    }
}

// ---------------- launch ----------------
extern "C" void kernel_launch(void* const* d_in, const int* in_sizes, int n_in,
                              void* d_out, int out_size) {
    const float* x     = (const float*)d_in[0];
    const float* dw_w  = (const float*)d_in[1];
    const float* dw_b  = (const float*)d_in[2];
    const float* pw_w  = (const float*)d_in[3];
    const float* pw_b  = (const float*)d_in[4];
    const float* ln_w  = (const float*)d_in[5];
    const float* ln_b  = (const float*)d_in[6];
    const float* l1_w  = (const float*)d_in[7];
    const float* l1_b  = (const float*)d_in[8];
    const float* gamma = (const float*)d_in[9];
    const float* beta  = (const float*)d_in[10];
    const float* l2_w  = (const float*)d_in[11];
    const float* l2_b  = (const float*)d_in[12];
    float* out = (float*)d_out;

    __half* buf1; cudaGetSymbolAddress((void**)&buf1, g_buf1);
    __half* buf2; cudaGetSymbolAddress((void**)&buf2, g_buf2);
    __half* buf3; cudaGetSymbolAddress((void**)&buf3, g_buf3);

    // raise dynamic smem limit (idempotent host-side attribute set)
    cudaFuncSetAttribute(gemm_tc<0>, cudaFuncAttributeMaxDynamicSharedMemorySize, SMEM_DYN);
    cudaFuncSetAttribute(gemm_tc<1>, cudaFuncAttributeMaxDynamicSharedMemorySize, SMEM_DYN);
    cudaFuncSetAttribute(gemm_tc<2>, cudaFuncAttributeMaxDynamicSharedMemorySize, SMEM_DYN);

    const int NB = (HWP + 127) / 128;   // 25

    // 1) depthwise conv -> buf1 (+ zero-init of reductions)
    dw_conv_kernel<<<dim3(1, 7, BB * CC), dim3(56, 8)>>>(x, dw_w, dw_b);

    // 2) pointwise 96->96 -> buf2 (+ fused LN stats)
    gemm_tc<0><<<dim3(NB, 1, BB), 256, SMEM_DYN>>>(pw_w, pw_b, buf1, buf2, CC, CC,
                                                   nullptr, nullptr, nullptr);

    // 3) expand 96->384 with fused LN on input + GELU -> buf3
    gemm_tc<1><<<dim3(NB, C4 / 96, BB), 256, SMEM_DYN>>>(l1_w, l1_b, buf2, buf3, C4, CC,
                                                         ln_w, ln_b, nullptr);

    // 4) sv estimates: streaming fp16 row-sum norm
    sv_rowsum_kernel<<<BB * C4, 64>>>();

    // 5) GRN affine + project 384->96 + bias + residual -> out
    gemm_tc<2><<<dim3(NB, 1, BB), 256, SMEM_DYN>>>(l2_w, l2_b, buf3, out, CC, C4,
                                                   gamma, beta, x);
}

// round 16
// speedup vs baseline: 1.2186x; 1.1515x over previous
#include <cuda_runtime.h>
#include <cuda_fp16.h>
#include <math.h>
#include <stdint.h>

#define BB   16
#define CC   96
#define C4   384
#define HH   56
#define WW   56
#define HWP  3136          // 56*56
#define CHW  301056        // 96*3136

// natural-major fp16 staged tiles (halves)
#define A_PITCH_H 40                   // 32 k + pad8  (80B row stride -> conflict-free LDSM)
#define B_PITCH_H 136                  // 128 n + pad8 (272B row stride -> conflict-free LDSM)
#define A_HALVES  (96 * A_PITCH_H)     // 3840
#define B_HALVES  (32 * B_PITCH_H)     // 4352
#define STAGE_HALVES (A_HALVES + B_HALVES)   // 8192
#define SMEM_DYN (2 * STAGE_HALVES * 2)      // 32768 bytes

// ---------------- scratch (device globals; no allocation) ----------------
__device__ __half g_buf1[BB * CC * HWP];   // dw out (fp16)
__device__ __half g_buf2[BB * CC * HWP];   // pw out, pre-LN (fp16)
__device__ __half g_buf3[BB * C4 * HWP];   // expand+gelu out (fp16)
__device__ double g_red[BB * 2];           // LN sum / sumsq per batch
__device__ float  g_sv[BB * C4];           // top-singular-value estimates
__device__ float  g_svsum;                 // sum of all sv

// ---------------- helpers ----------------
__device__ __forceinline__ float gelu_tanh_f(float x) {
    const float c = 0.7978845608028654f;
    float x3 = x * x * x;
    return 0.5f * x * (1.0f + tanhf(c * (x + 0.044715f * x3)));
}

__device__ __forceinline__ uint32_t smem_u32(const void* p) {
    uint32_t a;
    asm("{ .reg .u64 t; cvta.to.shared.u64 t, %1; cvt.u32.u64 %0, t; }" : "=r"(a) : "l"(p));
    return a;
}

__device__ __forceinline__ void ldsm_x4(unsigned* r, uint32_t addr) {
    asm volatile("ldmatrix.sync.aligned.m8n8.x4.shared.b16 {%0,%1,%2,%3}, [%4];"
        : "=r"(r[0]), "=r"(r[1]), "=r"(r[2]), "=r"(r[3]) : "r"(addr));
}

__device__ __forceinline__ void ldsm_x4_t(unsigned* r, uint32_t addr) {
    asm volatile("ldmatrix.sync.aligned.m8n8.x4.trans.shared.b16 {%0,%1,%2,%3}, [%4];"
        : "=r"(r[0]), "=r"(r[1]), "=r"(r[2]), "=r"(r[3]) : "r"(addr));
}

__device__ __forceinline__ void mma_fp16(float* c, const unsigned* a, const unsigned* b2) {
    asm volatile("mma.sync.aligned.m16n8k16.row.col.f32.f16.f16.f32 "
        "{%0,%1,%2,%3}, {%4,%5,%6,%7}, {%8,%9}, {%0,%1,%2,%3};"
        : "+f"(c[0]), "+f"(c[1]), "+f"(c[2]), "+f"(c[3])
        : "r"(a[0]), "r"(a[1]), "r"(a[2]), "r"(a[3]), "r"(b2[0]), "r"(b2[1]));
}

__device__ __forceinline__ uint2 pack4h(float4 v) {
    __half2 h01 = __floats2half2_rn(v.x, v.y);
    __half2 h23 = __floats2half2_rn(v.z, v.w);
    uint2 r;
    r.x = *reinterpret_cast<const unsigned*>(&h01);
    r.y = *reinterpret_cast<const unsigned*>(&h23);
    return r;
}

// ---------------- 1) depthwise 7x7 conv + bias (+ scratch zero-init) ----------------
__global__ void dw_conv_kernel(const float* __restrict__ x,
                               const float* __restrict__ dw_w,
                               const float* __restrict__ dw_b) {
    __shared__ float tile[14][62];
    __shared__ float sw[49];

    const int bc = blockIdx.z;
    const int c  = bc % CC;
    const int y0 = blockIdx.y * 8;
    const int tx = threadIdx.x;
    const int ty = threadIdx.y;
    const int tid = ty * 56 + tx;

    if (bc == 0 && blockIdx.y == 0) {
        if (tid < BB * 2) g_red[tid] = 0.0;
        if (tid == BB * 2) g_svsum = 0.0f;
    }

    const float* src = x + (size_t)bc * HWP;
    if (tid < 49) sw[tid] = dw_w[c * 49 + tid];

    for (int i = tid; i < 14 * 62; i += 448) {
        int r  = i / 62;
        int cx = i - r * 62;
        int gy = y0 - 3 + r;
        int gx = cx - 3;
        float v = 0.0f;
        if (gy >= 0 && gy < HH && gx >= 0 && gx < WW) v = src[gy * WW + gx];
        tile[r][cx] = v;
    }
    __syncthreads();

    float acc = dw_b[c];
    #pragma unroll
    for (int dy = 0; dy < 7; dy++)
        #pragma unroll
        for (int dx = 0; dx < 7; dx++)
            acc = fmaf(sw[dy * 7 + dx], tile[ty + dy][tx + dx], acc);

    g_buf1[(size_t)bc * HWP + (y0 + ty) * WW + tx] = __float2half(acc);
}

// ---------------- fp16 TC GEMM (m16n8k16 + ldmatrix), double-buffered ----------------
// out[b,m,n] = sum_k W[m,k]*in[b,k,n]
// MODE 0: +bias, fused LN sum/sumsq reduction, fp16 out    (pointwise)
// MODE 1: LN applied to B at staging, +bias, gelu, fp16 out (expand)
// MODE 2: B scaled by GRN affine, +bias, +residual, f32 out (project)
// grid: (ceil(HW/128), M/96, B), block: 256 (8 warps = 2m x 4n; warp tile 48x32)
template <int MODE>
__global__ __launch_bounds__(256)
void gemm_tc(const float* __restrict__ W,
             const float* __restrict__ bias,
             const __half* __restrict__ in,
             void* __restrict__ outv,
             int M, int K,
             const float* __restrict__ p0,   // MODE1: ln_w, MODE2: gamma
             const float* __restrict__ p1,   // MODE1: ln_b, MODE2: beta
             const float* __restrict__ resid) {
    extern __shared__ __half smem_h[];      // [2][STAGE_HALVES]: As then Bs per stage
    __shared__ double s_red[16];

    const int n0 = blockIdx.x * 128;
    const int m0 = blockIdx.y * 96;
    const int b  = blockIdx.z;
    const int tid  = threadIdx.x;
    const int lane = tid & 31;
    const int warp = tid >> 5;
    const int warp_m = warp >> 2;    // 0..1
    const int warp_n = warp & 3;     // 0..3

    const uint32_t smem_base = smem_u32(smem_h);

    const __half* inb = in + (size_t)b * K * HWP;
    const float inv_sum = (MODE == 2) ? (1.0f / g_svsum) : 0.0f;

    float mu = 0.0f, rs = 0.0f;
    if (MODE == 1) {
        double m_ = g_red[b * 2 + 0] / (double)CHW;
        double v_ = g_red[b * 2 + 1] / (double)CHW - m_ * m_;
        mu = (float)m_;
        rs = (float)(1.0 / sqrt(v_ + 1e-6));
    }

    float acc[3][4][4];
    #pragma unroll
    for (int mt = 0; mt < 3; mt++)
        #pragma unroll
        for (int nt = 0; nt < 4; nt++)
            #pragma unroll
            for (int j = 0; j < 4; j++) acc[mt][nt][j] = 0.0f;

    const int NK = K >> 5;
    float4 rA[3];
    uint2  rB[4];   // 4 halves each

    // ---- load tile k0 into registers ----
    auto load_tile = [&](int k0) {
        #pragma unroll
        for (int u = 0; u < 3; u++) {
            int i = tid + u * 256;
            int m = i >> 3, q = i & 7;
            rA[u] = *reinterpret_cast<const float4*>(&W[(size_t)(m0 + m) * K + k0 + q * 4]);
        }
        #pragma unroll
        for (int u = 0; u < 4; u++) {
            int i = tid + u * 256;
            int kk = i >> 5, nq = i & 31;
            int gn = n0 + nq * 4;
            rB[u] = (gn < HWP)
                  ? *reinterpret_cast<const uint2*>(inb + (size_t)(k0 + kk) * HWP + gn)
                  : make_uint2(0u, 0u);
        }
    };

    // ---- store registers into natural-major fp16 smem stage ----
    auto store_tile = [&](int k0, int stage) {
        __half* As = smem_h + stage * STAGE_HALVES;
        __half* Bs = As + A_HALVES;
        #pragma unroll
        for (int u = 0; u < 3; u++) {
            int i = tid + u * 256;
            int m = i >> 3, q = i & 7;
            *reinterpret_cast<uint2*>(&As[m * A_PITCH_H + q * 4]) = pack4h(rA[u]);
        }
        #pragma unroll
        for (int u = 0; u < 4; u++) {
            int i = tid + u * 256;
            int kk = i >> 5, nq = i & 31;
            uint2 pk = rB[u];
            if (MODE != 0) {
                int gn = n0 + nq * 4;
                float2 f01 = __half22float2(*reinterpret_cast<const __half2*>(&pk.x));
                float2 f23 = __half22float2(*reinterpret_cast<const __half2*>(&pk.y));
                float4 v = make_float4(f01.x, f01.y, f23.x, f23.y);
                if (MODE == 1) {
                    if (gn < HWP) {
                        size_t li = (size_t)(k0 + kk) * HWP + gn;
                        float4 lw = *reinterpret_cast<const float4*>(&p0[li]);
                        float4 lb = *reinterpret_cast<const float4*>(&p1[li]);
                        v.x = fmaf((v.x - mu) * rs, lw.x, lb.x);
                        v.y = fmaf((v.y - mu) * rs, lw.y, lb.y);
                        v.z = fmaf((v.z - mu) * rs, lw.z, lb.z);
                        v.w = fmaf((v.w - mu) * rs, lw.w, lb.w);
                    }
                }
                if (MODE == 2) {
                    int idx = b * C4 + k0 + kk;
                    float s  = fmaf(p0[idx] * g_sv[idx], inv_sum, 1.0f);
                    float sh = p1[idx];
                    v.x = fmaf(v.x, s, sh);
                    v.y = fmaf(v.y, s, sh);
                    v.z = fmaf(v.z, s, sh);
                    v.w = fmaf(v.w, s, sh);
                }
                pk = pack4h(v);
            }
            *reinterpret_cast<uint2*>(&Bs[kk * B_PITCH_H + nq * 4]) = pk;
        }
    };

    auto compute = [&](int stage) {
        const uint32_t As_u = smem_base + stage * STAGE_HALVES * 2;
        const uint32_t Bs_u = As_u + A_HALVES * 2;
        const int lr = lane & 15;        // row within 16
        const int lc = lane >> 4;        // column-half (k or n +8)
        #pragma unroll
        for (int ks = 0; ks < 2; ks++) {
            unsigned a[3][4];
            #pragma unroll
            for (int mt = 0; mt < 3; mt++) {
                uint32_t addr = As_u +
                    ((warp_m * 48 + mt * 16 + lr) * A_PITCH_H + ks * 16 + lc * 8) * 2;
                ldsm_x4(a[mt], addr);
            }
            unsigned bfr[2][4];
            #pragma unroll
            for (int np = 0; np < 2; np++) {
                uint32_t addr = Bs_u +
                    ((ks * 16 + lr) * B_PITCH_H + warp_n * 32 + np * 16 + lc * 8) * 2;
                ldsm_x4_t(bfr[np], addr);
            }
            #pragma unroll
            for (int mt = 0; mt < 3; mt++)
                #pragma unroll
                for (int nt = 0; nt < 4; nt++)
                    mma_fp16(acc[mt][nt], a[mt], &bfr[nt >> 1][(nt & 1) * 2]);
        }
    };

    // prologue: stage 0
    load_tile(0);
    store_tile(0, 0);
    __syncthreads();

    for (int it = 0; it < NK; it++) {
        const int stage = it & 1;
        if (it + 1 < NK) {
            load_tile((it + 1) << 5);   // LDG in flight during compute
            compute(stage);
            store_tile((it + 1) << 5, stage ^ 1);
        } else {
            compute(stage);
        }
        __syncthreads();
    }

    // ---- epilogue (C-fragment layout identical to m16n8k8) ----
    __half* outh = reinterpret_cast<__half*>(outv);
    float*  outf = reinterpret_cast<float*>(outv);

    float f1 = 0.0f, f2 = 0.0f;     // fp32 per-thread LN partials (24 values)
    #pragma unroll
    for (int mt = 0; mt < 3; mt++) {
        const int mA = m0 + warp_m * 48 + mt * 16 + (lane >> 2);
        const float biasA = bias[mA];
        const float biasB = bias[mA + 8];
        #pragma unroll
        for (int nt = 0; nt < 4; nt++) {
            const int n = n0 + warp_n * 32 + nt * 8 + 2 * (lane & 3);
            if (n < HWP) {
                #pragma unroll
                for (int rr = 0; rr < 2; rr++) {
                    const int mm = mA + rr * 8;
                    float v0 = acc[mt][nt][rr * 2 + 0] + (rr ? biasB : biasA);
                    float v1 = acc[mt][nt][rr * 2 + 1] + (rr ? biasB : biasA);
                    if (MODE == 1) { v0 = gelu_tanh_f(v0); v1 = gelu_tanh_f(v1); }
                    const size_t o = ((size_t)b * M + mm) * HWP + n;
                    if (MODE == 2) {
                        float2 r2 = *reinterpret_cast<const float2*>(&resid[o]);
                        v0 += r2.x; v1 += r2.y;
                        *reinterpret_cast<float2*>(&outf[o]) = make_float2(v0, v1);
                    } else {
                        *reinterpret_cast<__half2*>(&outh[o]) = __floats2half2_rn(v0, v1);
                    }
                    if (MODE == 0) {
                        f1 += v0 + v1;
                        f2 += v0 * v0 + v1 * v1;
                    }
                }
            }
        }
    }

    if (MODE == 0) {
        double s1 = (double)f1, s2 = (double)f2;
        #pragma unroll
        for (int off = 16; off > 0; off >>= 1) {
            s1 += __shfl_down_sync(0xffffffff, s1, off);
            s2 += __shfl_down_sync(0xffffffff, s2, off);
        }
        if (lane == 0) { s_red[warp] = s1; s_red[8 + warp] = s2; }
        __syncthreads();
        if (warp == 0) {
            double a1 = (lane < 8) ? s_red[lane] : 0.0;
            double a2 = (lane < 8) ? s_red[8 + lane] : 0.0;
            #pragma unroll
            for (int off = 4; off > 0; off >>= 1) {
                a1 += __shfl_down_sync(0xffffffff, a1, off);
                a2 += __shfl_down_sync(0xffffffff, a2, off);
            }
            if (lane == 0) {
                atomicAdd(&g_red[b * 2 + 0], a1);
                atomicAdd(&g_red[b * 2 + 1], a2);
            }
        }
    }
}

// ---------------- sv estimate: streaming fp16 row sums, 4 slices/block ----------------
// sigma ~= ||A v0|| = ||rowsums|| / sqrt(56), v0 = uniform unit vector.
// grid: B*C4/4 = 1536, block: 256 (4 groups of 64; one slice per group)
__global__ void sv_rowsum_kernel() {
    __shared__ float srow[4][56];

    const int grp = threadIdx.x >> 6;
    const int t   = threadIdx.x & 63;
    const int bc  = blockIdx.x * 4 + grp;
    const __half* src = g_buf3 + (size_t)bc * HWP;

    if (t < 56) {
        const uint4* p = reinterpret_cast<const uint4*>(src + t * 56);
        float s = 0.0f;
        #pragma unroll
        for (int j = 0; j < 7; j++) {
            uint4 q = p[j];
            float2 a = __half22float2(*reinterpret_cast<const __half2*>(&q.x));
            float2 b = __half22float2(*reinterpret_cast<const __half2*>(&q.y));
            float2 c = __half22float2(*reinterpret_cast<const __half2*>(&q.z));
            float2 d = __half22float2(*reinterpret_cast<const __half2*>(&q.w));
            s += a.x + a.y + b.x + b.y + c.x + c.y + d.x + d.y;
        }
        srow[grp][t] = s;
    }
    __syncthreads();

    // sigma = ||rowsums|| / sqrt(56): first warp of each group reduces
    if (t < 32) {
        float a  = srow[grp][t];
        float b2 = (t < 24) ? srow[grp][t + 32] : 0.0f;
        float p = a * a + b2 * b2;
        #pragma unroll
        for (int off = 16; off > 0; off >>= 1)
            p += __shfl_xor_sync(0xffffffff, p, off);
        if (t == 0) {
            float sigma = sqrtf(p) * 0.1336306f;   // * 1/sqrt(56)
            g_sv[bc] = sigma;
            atomicAdd(&g_svsum, sigma);
        }
    }
}

// ---------------- launch ----------------
extern "C" void kernel_launch(void* const* d_in, const int* in_sizes, int n_in,
                              void* d_out, int out_size) {
    const float* x     = (const float*)d_in[0];
    const float* dw_w  = (const float*)d_in[1];
    const float* dw_b  = (const float*)d_in[2];
    const float* pw_w  = (const float*)d_in[3];
    const float* pw_b  = (const float*)d_in[4];
    const float* ln_w  = (const float*)d_in[5];
    const float* ln_b  = (const float*)d_in[6];
    const float* l1_w  = (const float*)d_in[7];
    const float* l1_b  = (const float*)d_in[8];
    const float* gamma = (const float*)d_in[9];
    const float* beta  = (const float*)d_in[10];
    const float* l2_w  = (const float*)d_in[11];
    const float* l2_b  = (const float*)d_in[12];
    float* out = (float*)d_out;

    __half* buf1; cudaGetSymbolAddress((void**)&buf1, g_buf1);
    __half* buf2; cudaGetSymbolAddress((void**)&buf2, g_buf2);
    __half* buf3; cudaGetSymbolAddress((void**)&buf3, g_buf3);

    cudaFuncSetAttribute(gemm_tc<0>, cudaFuncAttributeMaxDynamicSharedMemorySize, SMEM_DYN);
    cudaFuncSetAttribute(gemm_tc<1>, cudaFuncAttributeMaxDynamicSharedMemorySize, SMEM_DYN);
    cudaFuncSetAttribute(gemm_tc<2>, cudaFuncAttributeMaxDynamicSharedMemorySize, SMEM_DYN);

    const int NB = (HWP + 127) / 128;   // 25

    // 1) depthwise conv -> buf1 (+ zero-init of reductions)
    dw_conv_kernel<<<dim3(1, 7, BB * CC), dim3(56, 8)>>>(x, dw_w, dw_b);

    // 2) pointwise 96->96 -> buf2 (+ fused LN stats)
    gemm_tc<0><<<dim3(NB, 1, BB), 256, SMEM_DYN>>>(pw_w, pw_b, buf1, buf2, CC, CC,
                                                   nullptr, nullptr, nullptr);

    // 3) expand 96->384 with fused LN on input + GELU -> buf3
    gemm_tc<1><<<dim3(NB, C4 / 96, BB), 256, SMEM_DYN>>>(l1_w, l1_b, buf2, buf3, C4, CC,
                                                         ln_w, ln_b, nullptr);

    // 4) sv estimates: streaming fp16 row-sum norm
    sv_rowsum_kernel<<<BB * C4 / 4, 256>>>();

    // 5) GRN affine + project 384->96 + bias + residual -> out
    gemm_tc<2><<<dim3(NB, 1, BB), 256, SMEM_DYN>>>(l2_w, l2_b, buf3, out, CC, C4,
                                                   gamma, beta, x);
}